// round 17
// baseline (speedup 1.0000x reference)
#include <cuda_runtime.h>
#include <cuda_bf16.h>
#include <cstdint>

#define BB 4
#define TE 512
#define TD 256
#define HE 128
#define HD 256
#define TT 4

// ---- scratch (device globals; no allocation allowed) ----
__device__ float g_TWsT[BB * HE * TE];      // tanh(enc @ W_a) transposed [B,HE,TE]
__device__ float g_TUh[BB * TD * HE];       // tanh(dec @ U_a)            [B,TD,HE]

__device__ __forceinline__ float fast_tanh(float x) {
    float y; asm("tanh.approx.f32 %0, %1;" : "=f"(y) : "f"(x)); return y;
}
__device__ __forceinline__ float fast_rcp(float x) {
    float r; asm("rcp.approx.ftz.f32 %0, %1;" : "=f"(r) : "f"(x)); return r;
}

// ====== Prep: TUh = tanh(dec@U), TWsT = tanh(enc@W)^T.  k-split, 256 thr ====
__global__ __launch_bounds__(256) void prep_kernel(
    const float* __restrict__ dec, const float* __restrict__ U,
    const float* __restrict__ enc, const float* __restrict__ W)
{
    __shared__ float sbuf[1024];                 // 4 KB staged input rows
    __shared__ float spart[1024];                // 4 KB k-split partials
    int tid = threadIdx.x;                       // 0..255
    int h   = tid >> 7;                          // k-half
    int f   = tid & 127;                         // output feature

    if (blockIdx.x < 256) {
        // ---- Uh: rows = B*TD, 4 per block, k in [h*128, h*128+128) ----
        int blk = blockIdx.x;
        int b  = blk >> 6;
        int t0 = (blk & 63) * 4;
        const float4* drow = reinterpret_cast<const float4*>(dec + ((size_t)b * TD + t0) * HD);
        reinterpret_cast<float4*>(sbuf)[tid] = drow[tid];
        __syncthreads();

        float a0 = 0.f, a1 = 0.f, a2 = 0.f, a3 = 0.f;
        int kb = h * 128;
#pragma unroll 8
        for (int k = kb; k < kb + 128; k += 2) {
            float u0 = U[(k + 0) * HE + f];
            float u1 = U[(k + 1) * HE + f];
            a0 = fmaf(sbuf[0 * HD + k], u0, a0); a0 = fmaf(sbuf[0 * HD + k + 1], u1, a0);
            a1 = fmaf(sbuf[1 * HD + k], u0, a1); a1 = fmaf(sbuf[1 * HD + k + 1], u1, a1);
            a2 = fmaf(sbuf[2 * HD + k], u0, a2); a2 = fmaf(sbuf[2 * HD + k + 1], u1, a2);
            a3 = fmaf(sbuf[3 * HD + k], u0, a3); a3 = fmaf(sbuf[3 * HD + k + 1], u1, a3);
        }
        if (h == 1) {
            spart[0 * HE + f] = a0; spart[1 * HE + f] = a1;
            spart[2 * HE + f] = a2; spart[3 * HE + f] = a3;
        }
        __syncthreads();
        if (h == 0) {
            size_t base = ((size_t)(b * TD + t0)) * HE + f;
            g_TUh[base + 0 * HE] = fast_tanh(a0 + spart[0 * HE + f]);
            g_TUh[base + 1 * HE] = fast_tanh(a1 + spart[1 * HE + f]);
            g_TUh[base + 2 * HE] = fast_tanh(a2 + spart[2 * HE + f]);
            g_TUh[base + 3 * HE] = fast_tanh(a3 + spart[3 * HE + f]);
        }
    } else {
        // ---- Ws: rows = B*TE, 8 per block, k in [h*64, h*64+64) ----
        int blk = blockIdx.x - 256;
        int b  = blk >> 6;
        int s0 = (blk & 63) * 8;
        const float4* erow = reinterpret_cast<const float4*>(enc + ((size_t)b * TE + s0) * HE);
        reinterpret_cast<float4*>(sbuf)[tid] = erow[tid];
        __syncthreads();

        float acc[8];
#pragma unroll
        for (int r = 0; r < 8; r++) acc[r] = 0.f;
        int kb = h * 64;
#pragma unroll 4
        for (int k = kb; k < kb + 64; k += 2) {
            float w0 = W[(k + 0) * HE + f];
            float w1 = W[(k + 1) * HE + f];
#pragma unroll
            for (int r = 0; r < 8; r++) {
                float aa = acc[r];
                aa = fmaf(sbuf[r * HE + k], w0, aa);
                aa = fmaf(sbuf[r * HE + k + 1], w1, aa);
                acc[r] = aa;
            }
        }
        if (h == 1) {
#pragma unroll
            for (int r = 0; r < 8; r++) spart[r * HE + f] = acc[r];
        }
        __syncthreads();
        if (h == 0) {
            size_t base = ((size_t)b * HE + f) * TE + s0;   // transposed [b][f][s]
#pragma unroll
            for (int r = 0; r < 8; r++)
                g_TWsT[base + r] = fast_tanh(acc[r] + spart[r * HE + f]);
        }
    }
}

// ====== Fused: partial-fraction identity.  score = sum_f c_tf/(1+w*u) ======
// tanh(w+u) = (w+u)/(1+wu) = 1/u + (u-1/u)/(1+wu); the sum_f v/u term is
// constant per t -> dropped (softmax shift-invariant; only weights output).
// c_tf = v_f*(u-1/u) precomputed per CTA; |u| clamped >= 1e-3 for stability.
__global__ __launch_bounds__(512, 2) void score_ctx_kernel(
    const float* __restrict__ enc,
    const float* __restrict__ Va,
    float* __restrict__ c_out,   // [B,TD,HE]
    float* __restrict__ e_out)   // [B,TD,TE]
{
    __shared__ float s_tu[TT * HE];              // 2 KB  clamped u
    __shared__ float s_c[TT * HE];               // 2 KB  c_tf
    __shared__ float s_scores[TT * TE];          // 8 KB
    __shared__ float s_ctx[4][TT * HE];          // 8 KB

    int blk = blockIdx.x;
    int b  = blk / (TD / TT);
    int t0 = (blk % (TD / TT)) * TT;
    int tid  = threadIdx.x;                      // 0..511 == encoder position s
    int warp = tid >> 5;
    int lane = tid & 31;

    // ---- Phase 0: load u, clamp, build c table ----
    {
        float u = g_TUh[((size_t)(b * TD + t0)) * HE + tid];   // (t,f) = tid
        if (fabsf(u) < 1e-3f) u = copysignf(1e-3f, u);
        float v = Va[tid & 127];
        s_tu[tid] = u;
        s_c[tid]  = v * (u - 1.0f / u);
    }
    __syncthreads();

    const float4* tu4 = reinterpret_cast<const float4*>(s_tu);
    const float4* c4p = reinterpret_cast<const float4*>(s_c);

    // ---- Phase 1: acc_t += c_tf * rcp(1 + w*u_tf) ----
    {
        const float* wcol = g_TWsT + (size_t)b * HE * TE + tid;   // + f*TE
        float acc0 = 0.f, acc1 = 0.f, acc2 = 0.f, acc3 = 0.f;

#pragma unroll 8
        for (int q = 0; q < HE / 4; q++) {
            float wx = wcol[(4 * q + 0) * TE];
            float wy = wcol[(4 * q + 1) * TE];
            float wz = wcol[(4 * q + 2) * TE];
            float ww = wcol[(4 * q + 3) * TE];
            // t-pair (0,1): pairwise reciprocal
            {
                float4 u0 = tu4[0 * (HE / 4) + q], c0 = c4p[0 * (HE / 4) + q];
                float4 u1 = tu4[1 * (HE / 4) + q], c1 = c4p[1 * (HE / 4) + q];
                float d0, d1, r;
                d0 = fmaf(wx, u0.x, 1.f); d1 = fmaf(wx, u1.x, 1.f); r = fast_rcp(d0 * d1);
                acc0 = fmaf(c0.x * d1, r, acc0); acc1 = fmaf(c1.x * d0, r, acc1);
                d0 = fmaf(wy, u0.y, 1.f); d1 = fmaf(wy, u1.y, 1.f); r = fast_rcp(d0 * d1);
                acc0 = fmaf(c0.y * d1, r, acc0); acc1 = fmaf(c1.y * d0, r, acc1);
                d0 = fmaf(wz, u0.z, 1.f); d1 = fmaf(wz, u1.z, 1.f); r = fast_rcp(d0 * d1);
                acc0 = fmaf(c0.z * d1, r, acc0); acc1 = fmaf(c1.z * d0, r, acc1);
                d0 = fmaf(ww, u0.w, 1.f); d1 = fmaf(ww, u1.w, 1.f); r = fast_rcp(d0 * d1);
                acc0 = fmaf(c0.w * d1, r, acc0); acc1 = fmaf(c1.w * d0, r, acc1);
            }
            // t = 2, 3: plain reciprocal (balances MUFU vs FMA pipes)
            {
                float4 u2 = tu4[2 * (HE / 4) + q], c2 = c4p[2 * (HE / 4) + q];
                float4 u3 = tu4[3 * (HE / 4) + q], c3 = c4p[3 * (HE / 4) + q];
                acc2 = fmaf(c2.x, fast_rcp(fmaf(wx, u2.x, 1.f)), acc2);
                acc3 = fmaf(c3.x, fast_rcp(fmaf(wx, u3.x, 1.f)), acc3);
                acc2 = fmaf(c2.y, fast_rcp(fmaf(wy, u2.y, 1.f)), acc2);
                acc3 = fmaf(c3.y, fast_rcp(fmaf(wy, u3.y, 1.f)), acc3);
                acc2 = fmaf(c2.z, fast_rcp(fmaf(wz, u2.z, 1.f)), acc2);
                acc3 = fmaf(c3.z, fast_rcp(fmaf(wz, u3.z, 1.f)), acc3);
                acc2 = fmaf(c2.w, fast_rcp(fmaf(ww, u2.w, 1.f)), acc2);
                acc3 = fmaf(c3.w, fast_rcp(fmaf(ww, u3.w, 1.f)), acc3);
            }
        }
        s_scores[0 * TE + tid] = acc0;
        s_scores[1 * TE + tid] = acc1;
        s_scores[2 * TE + tid] = acc2;
        s_scores[3 * TE + tid] = acc3;
    }
    __syncthreads();

    // ---- Phase 2: softmax per decoder step (warps 0..3) ----
    if (warp < TT) {
        int t = warp;
        float* sc = s_scores + t * TE;
        float m = -1e30f;
        for (int s = lane; s < TE; s += 32) m = fmaxf(m, sc[s]);
#pragma unroll
        for (int o = 16; o > 0; o >>= 1)
            m = fmaxf(m, __shfl_xor_sync(0xFFFFFFFFu, m, o));
        float sum = 0.f;
        for (int s = lane; s < TE; s += 32) {
            float ex = __expf(sc[s] - m);
            sc[s] = ex;
            sum += ex;
        }
#pragma unroll
        for (int o = 16; o > 0; o >>= 1)
            sum += __shfl_xor_sync(0xFFFFFFFFu, sum, o);
        float inv = 1.0f / sum;
        float* eo = e_out + ((size_t)(b * TD + t0 + t)) * TE;
        for (int s = lane; s < TE; s += 32) {
            float w = sc[s] * inv;
            sc[s] = w;
            eo[s] = w;
        }
    }
    __syncthreads();

    // ---- Phase 3: context. 4 groups of 128 threads split the s-range. ----
    {
        int g  = tid >> 7;              // 0..3
        int ee = tid & 127;             // output feature
        const float* encb = enc + (size_t)b * TE * HE;
        float a0 = 0.f, a1 = 0.f, a2 = 0.f, a3 = 0.f;
        int sbeg = g * (TE / 4);
#pragma unroll 2
        for (int s = sbeg; s < sbeg + TE / 4; s += 4) {
            float4 w0 = *reinterpret_cast<const float4*>(&s_scores[0 * TE + s]);
            float4 w1 = *reinterpret_cast<const float4*>(&s_scores[1 * TE + s]);
            float4 w2 = *reinterpret_cast<const float4*>(&s_scores[2 * TE + s]);
            float4 w3 = *reinterpret_cast<const float4*>(&s_scores[3 * TE + s]);
            float x0 = encb[(size_t)(s + 0) * HE + ee];
            float x1 = encb[(size_t)(s + 1) * HE + ee];
            float x2 = encb[(size_t)(s + 2) * HE + ee];
            float x3 = encb[(size_t)(s + 3) * HE + ee];
            a0 = fmaf(w0.x, x0, fmaf(w0.y, x1, fmaf(w0.z, x2, fmaf(w0.w, x3, a0))));
            a1 = fmaf(w1.x, x0, fmaf(w1.y, x1, fmaf(w1.z, x2, fmaf(w1.w, x3, a1))));
            a2 = fmaf(w2.x, x0, fmaf(w2.y, x1, fmaf(w2.z, x2, fmaf(w2.w, x3, a2))));
            a3 = fmaf(w3.x, x0, fmaf(w3.y, x1, fmaf(w3.z, x2, fmaf(w3.w, x3, a3))));
        }
        s_ctx[g][0 * HE + ee] = a0;
        s_ctx[g][1 * HE + ee] = a1;
        s_ctx[g][2 * HE + ee] = a2;
        s_ctx[g][3 * HE + ee] = a3;
    }
    __syncthreads();

    {
        float r = s_ctx[0][tid] + s_ctx[1][tid] + s_ctx[2][tid] + s_ctx[3][tid];
        int tt = tid >> 7;
        int ee = tid & 127;
        c_out[((size_t)(b * TD + t0 + tt)) * HE + ee] = r;
    }
}

extern "C" void kernel_launch(void* const* d_in, const int* in_sizes, int n_in,
                              void* d_out, int out_size) {
    const float* enc = (const float*)d_in[0];   // [B,TE,HE]
    const float* dec = (const float*)d_in[1];   // [B,TD,HD]
    const float* Wa  = (const float*)d_in[2];   // [HE,HE]
    const float* Ua  = (const float*)d_in[3];   // [HD,HE]
    const float* Va  = (const float*)d_in[4];   // [HE,1]

    float* out   = (float*)d_out;
    float* c_out = out;                          // [B,TD,HE]
    float* e_out = out + (size_t)BB * TD * HE;   // [B,TD,TE]

    prep_kernel<<<512, 256>>>(dec, Ua, enc, Wa);
    score_ctx_kernel<<<BB * (TD / TT), 512>>>(enc, Va, c_out, e_out);
}